// round 3
// baseline (speedup 1.0000x reference)
#include <cuda_runtime.h>
#include <math.h>
#include <stdint.h>

#define BATCH 16
#define KBOX  128
#define NUMC  80
#define OH    128
#define OW    128
#define NB    (BATCH*KBOX)
#define PLANE (OH*OW)

// ---- per-box scratch (sorted order) ----
__device__ float d_bx1[NB], d_by1[NB], d_bx2[NB], d_by2[NB];
__device__ float d_i2sy[NB], d_i2sx[NB], d_coef[NB];
__device__ int   d_cls[NB], d_cx[NB], d_cy[NB], d_hr[NB], d_wr[NB], d_act[NB];

// ---- global accumulators ----
__device__ double d_acc_hm;
__device__ double d_acc_whn;
__device__ double d_acc_rw;
__device__ int    d_acc_np;

// =====================================================================
// Kernel 1: fused zero + mask decode + per-image sort + per-box params.
// grid=(BATCH), 128 threads.  Each block sniffs the mask dtype from the
// first 2048 bytes (in-bounds for any dtype >= 1B), decodes its slice.
//   any byte > 1                      -> 4-byte dtype (f32; word-nonzero)
//   else nonzero byte at i%4 != 0     -> u8 bool
//   else                              -> 4-byte (i32; word-nonzero; also
//                                        correct for f32 0.0/1.0 patterns)
// =====================================================================
__global__ void prep_kernel(const float* __restrict__ tgt,
                            const void* __restrict__ mraw) {
    int b = blockIdx.x;
    int k = threadIdx.x;
    __shared__ float skey[KBOX];
    __shared__ int   sperm[KBOX];
    __shared__ int   smask[KBOX];
    __shared__ float s_al0;
    __shared__ int   s_gt1, s_off4;

    if (b == 0 && k == 0) {
        d_acc_hm = 0.0; d_acc_whn = 0.0; d_acc_rw = 0.0; d_acc_np = 0;
    }

    // ---- dtype sniff over first NB bytes ----
    if (k == 0) { s_gt1 = 0; s_off4 = 0; }
    __syncthreads();
    {
        const uint8_t* b8 = (const uint8_t*)mraw;
        int gt1 = 0, off4 = 0;
        for (int i = k; i < NB; i += KBOX) {
            uint8_t v = b8[i];
            gt1  |= (v > 1);
            off4 |= (v != 0) && ((i & 3) != 0);
        }
        if (gt1)  atomicOr(&s_gt1, 1);
        if (off4) atomicOr(&s_off4, 1);
    }
    __syncthreads();
    int u8mode = (!s_gt1) && s_off4;
    {
        int i = b*KBOX + k;
        int v;
        if (u8mode) v = (((const uint8_t*)mraw)[i] != 0);
        else        v = (((const uint32_t*)mraw)[i] != 0u);
        smask[k] = v;
    }
    __syncthreads();

    const float* t = tgt + (size_t)(b*KBOX + k)*5;
    float x1 = t[1], y1 = t[2], x2 = t[3], y2 = t[4];
    int valid = smask[k];
    float area = (x2 - x1) * (y2 - y1);
    float key = valid ? logf(area) : -INFINITY;
    skey[k] = key;
    __syncthreads();

    // stable descending rank
    int rank = 0;
#pragma unroll 8
    for (int j = 0; j < KBOX; j++) {
        float kj = skey[j];
        rank += (kj > key) || (kj == key && j < k);
    }
    sperm[rank] = k;
    __syncthreads();

    if (k == 0) {
        int o0 = sperm[0];
        s_al0 = smask[o0] ? skey[o0] : 0.0f;
    }
    __syncthreads();

    int o = sperm[k];
    const float* to = tgt + (size_t)(b*KBOX + o)*5;
    float clsf = to[0];
    float ox1 = to[1], oy1 = to[2], ox2 = to[3], oy2 = to[4];
    int v = smask[o];
    float keyo = skey[o];

    float fx1 = fminf(fmaxf(ox1 * 0.25f, 0.0f), (float)(OW-1));
    float fy1 = fminf(fmaxf(oy1 * 0.25f, 0.0f), (float)(OH-1));
    float fx2 = fminf(fmaxf(ox2 * 0.25f, 0.0f), (float)(OW-1));
    float fy2 = fminf(fmaxf(oy2 * 0.25f, 0.0f), (float)(OH-1));
    float feat_h = fy2 - fy1;
    float feat_w = fx2 - fx1;

    int cx = (int)(((ox1 + ox2) * 0.5f) * 0.25f);
    int cy = (int)(((oy1 + oy2) * 0.5f) * 0.25f);
    int hr = (int)((feat_h * 0.5f) * 0.54f);
    int wr = (int)((feat_w * 0.5f) * 0.54f);
    float sy = (float)(2*hr + 1) / 6.0f;
    float sx = (float)(2*wr + 1) / 6.0f;
    float i2sy = 1.0f / (2.0f * sy * sy);
    float i2sx = 1.0f / (2.0f * sx * sx);

    int act = v && (cx >= 0) && (cx < OW) && (cy >= 0) && (cy < OH);

    float divs = 0.0f;
    if (act) {
        float sgy = 0.0f, sgx = 0.0f;
        int ya = max(0, cy - hr), yb = min(OH-1, cy + hr);
        for (int yy = ya; yy <= yb; yy++) {
            float d = (float)(yy - cy);
            sgy += __expf(-(d*d) * i2sy);
        }
        int xa = max(0, cx - wr), xb = min(OW-1, cx + wr);
        for (int xx = xa; xx <= xb; xx++) {
            float d = (float)(xx - cx);
            sgx += __expf(-(d*d) * i2sx);
        }
        divs = sgy * sgx;
    }
    float al = v ? keyo : 0.0f;
    float factor = 2.0f - al / (s_al0 + 1e-7f);
    float coef = act ? (factor / (divs + 1e-7f)) : 0.0f;

    int idx = b*KBOX + k;
    d_bx1[idx] = ox1; d_by1[idx] = oy1; d_bx2[idx] = ox2; d_by2[idx] = oy2;
    d_i2sy[idx] = i2sy; d_i2sx[idx] = i2sx; d_coef[idx] = coef;
    d_cls[idx] = (int)clsf; d_cx[idx] = cx; d_cy[idx] = cy;
    d_hr[idx] = hr; d_wr[idx] = wr; d_act[idx] = act;
}

// u(x) = log(1 - clip(sigmoid(x))) * clip(sigmoid(x))^2   (3 MUFU)
__device__ __forceinline__ float focal_neg_base(float xv, float& p_out) {
    float t = __expf(-xv);
    float p = __fdividef(1.0f, 1.0f + t);
    p = fminf(fmaxf(p, 1e-4f), 0.9999f);
    p_out = p;
    float omp = 1.0f - p;
    return __logf(omp) * p * p;
}

// =====================================================================
// Kernel 2: main fused loss.  grid=(OH/4, BATCH), 128 threads.
// Warp w owns row y0+w; lane owns 4 consecutive x (float4).
// =====================================================================
__global__ void __launch_bounds__(128) loss_kernel(const float* __restrict__ hm,
                                                   const float* __restrict__ wh) {
    int b = blockIdx.y;
    int y0 = blockIdx.x * 4;
    int t = threadIdx.x;
    int w = t >> 5, lane = t & 31;
    int y = y0 + w;
    int xbase = lane * 4;

    __shared__ float sx1[KBOX], sy1s[KBOX], sx2[KBOX], sy2s[KBOX];
    __shared__ float scoef[KBOX], si2sx[KBOX];
    __shared__ int   scx[KBOX], swr[KBOX], scls[KBOX];
    __shared__ float sgy4[4][KBOX];
    __shared__ short slist[4][KBOX];

    // load box t's data, compute row gaussians for all 4 rows
    {
        int base = b*KBOX + t;
        float i2sy = d_i2sy[base];
        int cy = d_cy[base], hr = d_hr[base], act = d_act[base];
        sx1[t] = d_bx1[base]; sy1s[t] = d_by1[base];
        sx2[t] = d_bx2[base]; sy2s[t] = d_by2[base];
        scoef[t] = d_coef[base]; si2sx[t] = d_i2sx[base];
        scx[t] = d_cx[base]; swr[t] = d_wr[base]; scls[t] = d_cls[base];
#pragma unroll
        for (int r = 0; r < 4; r++) {
            int dy = y0 + r - cy;
            int rc = act && (abs(dy) <= hr);
            sgy4[r][t] = rc ? __expf(-(float)(dy*dy) * i2sy) : 0.0f;
        }
    }
    __syncthreads();

    // warp w builds its row's covering-box list (ballot compaction)
    int n = 0;
#pragma unroll
    for (int chunk = 0; chunk < 4; chunk++) {
        int j = chunk*32 + lane;
        bool p = sgy4[w][j] > 0.0f;
        unsigned mb = __ballot_sync(0xffffffffu, p);
        int pos = n + __popc(mb & ((1u << lane) - 1u));
        if (p) slist[w][pos] = (short)j;
        n += __popc(mb);
    }

    float lsum = 0.0f;
    int   lnp  = 0;

    // ---- focal base term over all classes, float4 per thread ----
    const float* hmp = hm + (((size_t)b*NUMC)*OH + y)*OW + xbase;
#pragma unroll 8
    for (int c = 0; c < NUMC; c++) {
        float4 hv = *(const float4*)(hmp + (size_t)c * PLANE);
        float p;
        lsum += focal_neg_base(hv.x, p);
        lsum += focal_neg_base(hv.y, p);
        lsum += focal_neg_base(hv.z, p);
        lsum += focal_neg_base(hv.w, p);
    }

    // ---- wh planes (float4, unconditional) ----
    size_t wbase = (((size_t)b*4)*OH + y)*OW + xbase;
    float4 w0 = *(const float4*)(wh + wbase);
    float4 w1 = *(const float4*)(wh + wbase +   PLANE);
    float4 w2 = *(const float4*)(wh + wbase + 2*PLANE);
    float4 w3 = *(const float4*)(wh + wbase + 3*PLANE);
    float lwhn = 0.0f, lrw = 0.0f;

    const short* mylist = slist[w];
    const float* mysgy  = sgy4[w];

    for (int i = 0; i < 4; i++) {
        int x = xbase + i;
        // coverage + winner
        unsigned covm[4] = {0u,0u,0u,0u};
        int e_w = -1;
        for (int e = 0; e < n; e++) {
            int j = mylist[e];
            int dx = x - scx[j];
            if (abs(dx) <= swr[j]) {
                covm[e >> 5] |= 1u << (e & 31);
                e_w = e;
            }
        }
        // corrections
        for (int e = 0; e < n; e++) {
            if (!((covm[e >> 5] >> (e & 31)) & 1u)) continue;
            int j = mylist[e];
            int c = scls[j];
            float dxf = (float)(x - scx[j]);
            float g = mysgy[j] * __expf(-dxf*dxf * si2sx[j]);
            bool rep = true;
            for (int e2 = 0; e2 < n; e2++) {
                if (e2 == e) continue;
                if (!((covm[e2 >> 5] >> (e2 & 31)) & 1u)) continue;
                int j2 = mylist[e2];
                if (scls[j2] != c) continue;
                float dx2 = (float)(x - scx[j2]);
                float g2 = mysgy[j2] * __expf(-dx2*dx2 * si2sx[j2]);
                if (g2 > g || (g2 == g && e2 < e)) { rep = false; break; }
            }
            if (!rep) continue;
            float xv = hmp[(size_t)c * PLANE + i];
            float p;
            float u = focal_neg_base(xv, p);
            if (g == 1.0f) {
                float omp = 1.0f - p;
                float vv = __logf(p) * omp * omp;
                lsum += vv - u;
                lnp++;
            } else {
                float omh = 1.0f - g;
                float w4 = omh * omh; w4 *= w4;
                lsum += u * (w4 - 1.0f);
            }
        }
        // wh / IoU at winner pixel
        if (e_w >= 0) {
            int j = mylist[e_w];
            float dxf = (float)(x - scx[j]);
            float g = mysgy[j] * __expf(-dxf*dxf * si2sx[j]);
            float rw = g * scoef[j];
            float pl = (&w0.x)[i] * 16.0f;
            float pt = (&w1.x)[i] * 16.0f;
            float pr = (&w2.x)[i] * 16.0f;
            float pb = (&w3.x)[i] * 16.0f;
            float xs = (float)x * 4.0f, ys = (float)y * 4.0f;
            float tl = xs - sx1[j];
            float tt = ys - sy1s[j];
            float tr = sx2[j] - xs;
            float tb = sy2s[j] - ys;
            float ta = (tl + tr) * (tt + tb);
            float pa = (pl + pr) * (pt + pb);
            float wi = fminf(pl, tl) + fminf(pr, tr);
            float hi = fminf(pt, tt) + fminf(pb, tb);
            float ai = wi * hi;
            float au = ta + pa - ai;
            float iou = (ai + 1.0f) / (au + 1.0f);
            lwhn += (rw > 0.0f) ? (1.0f - iou) * rw : 0.0f;
            lrw  += rw;
        }
    }

    // ---- block reduce -> double atomics ----
    for (int off = 16; off; off >>= 1) {
        lsum += __shfl_down_sync(0xffffffffu, lsum, off);
        lwhn += __shfl_down_sync(0xffffffffu, lwhn, off);
        lrw  += __shfl_down_sync(0xffffffffu, lrw,  off);
        lnp  += __shfl_down_sync(0xffffffffu, lnp,  off);
    }
    __shared__ float r0[4], r1[4], r2[4];
    __shared__ int   r3[4];
    if (lane == 0) { r0[w]=lsum; r1[w]=lwhn; r2[w]=lrw; r3[w]=lnp; }
    __syncthreads();
    if (t == 0) {
        float a=0.f, c1=0.f, c2=0.f; int np=0;
        for (int i = 0; i < 4; i++) { a+=r0[i]; c1+=r1[i]; c2+=r2[i]; np+=r3[i]; }
        atomicAdd(&d_acc_hm,  (double)a);
        atomicAdd(&d_acc_whn, (double)c1);
        atomicAdd(&d_acc_rw,  (double)c2);
        atomicAdd(&d_acc_np,  np);
    }
}

__global__ void final_kernel(float* out) {
    double hm_sum = d_acc_hm;
    int np = d_acc_np;
    double hml;
    if (np > 0) hml = -hm_sum / (double)(np < 1 ? 1 : np);
    else        hml = -hm_sum;
    double whl = d_acc_whn / fmax(d_acc_rw, 1.0);
    out[0] = (float)(hml + whl);
}

extern "C" void kernel_launch(void* const* d_in, const int* in_sizes, int n_in,
                              void* d_out, int out_size) {
    const float* hm   = (const float*)d_in[0];
    const float* wh   = (const float*)d_in[1];
    const float* tgt  = (const float*)d_in[2];
    const void*  mask = (const void*)d_in[3];
    float* out = (float*)d_out;
    (void)in_sizes; (void)n_in; (void)out_size;

    prep_kernel<<<BATCH, KBOX>>>(tgt, mask);
    loss_kernel<<<dim3(OH/4, BATCH), 128>>>(hm, wh);
    final_kernel<<<1, 1>>>(out);
}

// round 4
// speedup vs baseline: 3.2713x; 3.2713x over previous
#include <cuda_runtime.h>
#include <math.h>
#include <stdint.h>

#define BATCH 16
#define KBOX  128
#define NUMC  80
#define OH    128
#define OW    128
#define NB    (BATCH*KBOX)
#define PLANE (OH*OW)
#define TOT4  (BATCH*NUMC*PLANE/4)   // 5,242,880 float4
#define BASE_BLK 2560                // TOT4 / (256*8)

// ---- per-box scratch (sorted order) ----
__device__ float d_bx1[NB], d_by1[NB], d_bx2[NB], d_by2[NB];
__device__ float d_i2sy[NB], d_i2sx[NB], d_coef[NB];
__device__ int   d_cls[NB], d_cx[NB], d_cy[NB], d_hr[NB], d_wr[NB], d_act[NB];

// ---- global accumulators ----
__device__ double d_acc_hm;
__device__ double d_acc_whn;
__device__ double d_acc_rw;
__device__ int    d_acc_np;

// u(x) = log(1 - clip(sigmoid(x))) * clip(sigmoid(x))^2   (3 MUFU)
__device__ __forceinline__ float focal_neg_base(float xv, float& p_out) {
    float t = __expf(-xv);
    float p = __fdividef(1.0f, 1.0f + t);
    p = fminf(fmaxf(p, 1e-4f), 0.9999f);
    p_out = p;
    float omp = 1.0f - p;
    return __logf(omp) * p * p;
}

// =====================================================================
// Kernel 1: fused zero + mask decode + per-image sort + per-box params.
// =====================================================================
__global__ void prep_kernel(const float* __restrict__ tgt,
                            const void* __restrict__ mraw) {
    int b = blockIdx.x;
    int k = threadIdx.x;
    __shared__ float skey[KBOX];
    __shared__ int   sperm[KBOX];
    __shared__ int   smask[KBOX];
    __shared__ float s_al0;
    __shared__ int   s_gt1, s_off4;

    if (b == 0 && k == 0) {
        d_acc_hm = 0.0; d_acc_whn = 0.0; d_acc_rw = 0.0; d_acc_np = 0;
    }

    // ---- dtype sniff over first NB bytes (in-bounds for any dtype >= 1B) ----
    if (k == 0) { s_gt1 = 0; s_off4 = 0; }
    __syncthreads();
    {
        const uint8_t* b8 = (const uint8_t*)mraw;
        int gt1 = 0, off4 = 0;
#pragma unroll
        for (int c = 0; c < NB/KBOX; c++) {
            int i = c*KBOX + k;
            uint8_t v = b8[i];
            gt1  |= (v > 1);
            off4 |= (v != 0) && ((i & 3) != 0);
        }
        if (gt1)  atomicOr(&s_gt1, 1);
        if (off4) atomicOr(&s_off4, 1);
    }
    __syncthreads();
    int u8mode = (!s_gt1) && s_off4;
    {
        int i = b*KBOX + k;
        smask[k] = u8mode ? (((const uint8_t*)mraw)[i] != 0)
                          : (((const uint32_t*)mraw)[i] != 0u);
    }
    __syncthreads();

    const float* t = tgt + (size_t)(b*KBOX + k)*5;
    float x1 = t[1], y1 = t[2], x2 = t[3], y2 = t[4];
    int valid = smask[k];
    float area = (x2 - x1) * (y2 - y1);
    float key = valid ? __logf(area) : -INFINITY;
    skey[k] = key;
    __syncthreads();

    // stable descending rank
    int rank = 0;
#pragma unroll 16
    for (int j = 0; j < KBOX; j++) {
        float kj = skey[j];
        rank += (kj > key) || (kj == key && j < k);
    }
    sperm[rank] = k;
    __syncthreads();

    if (k == 0) {
        int o0 = sperm[0];
        s_al0 = smask[o0] ? skey[o0] : 0.0f;
    }
    __syncthreads();

    int o = sperm[k];
    const float* to = tgt + (size_t)(b*KBOX + o)*5;
    float clsf = to[0];
    float ox1 = to[1], oy1 = to[2], ox2 = to[3], oy2 = to[4];
    int v = smask[o];
    float keyo = skey[o];

    float fx1 = fminf(fmaxf(ox1 * 0.25f, 0.0f), (float)(OW-1));
    float fy1 = fminf(fmaxf(oy1 * 0.25f, 0.0f), (float)(OH-1));
    float fx2 = fminf(fmaxf(ox2 * 0.25f, 0.0f), (float)(OW-1));
    float fy2 = fminf(fmaxf(oy2 * 0.25f, 0.0f), (float)(OH-1));
    float feat_h = fy2 - fy1;
    float feat_w = fx2 - fx1;

    int cx = (int)(((ox1 + ox2) * 0.5f) * 0.25f);
    int cy = (int)(((oy1 + oy2) * 0.5f) * 0.25f);
    int hr = (int)((feat_h * 0.5f) * 0.54f);
    int wr = (int)((feat_w * 0.5f) * 0.54f);
    float sy = (float)(2*hr + 1) / 6.0f;
    float sx = (float)(2*wr + 1) / 6.0f;
    float i2sy = 1.0f / (2.0f * sy * sy);
    float i2sx = 1.0f / (2.0f * sx * sx);

    int act = v && (cx >= 0) && (cx < OW) && (cy >= 0) && (cy < OH);

    float divs = 0.0f;
    if (act) {
        float sgy = 0.0f, sgx = 0.0f;
        int ya = max(0, cy - hr), yb = min(OH-1, cy + hr);
        for (int yy = ya; yy <= yb; yy++) {
            float d = (float)(yy - cy);
            sgy += __expf(-(d*d) * i2sy);
        }
        int xa = max(0, cx - wr), xb = min(OW-1, cx + wr);
        for (int xx = xa; xx <= xb; xx++) {
            float d = (float)(xx - cx);
            sgx += __expf(-(d*d) * i2sx);
        }
        divs = sgy * sgx;
    }
    float al = v ? keyo : 0.0f;
    float factor = 2.0f - al / (s_al0 + 1e-7f);
    float coef = act ? (factor / (divs + 1e-7f)) : 0.0f;

    int idx = b*KBOX + k;
    d_bx1[idx] = ox1; d_by1[idx] = oy1; d_bx2[idx] = ox2; d_by2[idx] = oy2;
    d_i2sy[idx] = i2sy; d_i2sx[idx] = i2sx; d_coef[idx] = coef;
    d_cls[idx] = (int)clsf; d_cx[idx] = cx; d_cy[idx] = cy;
    d_hr[idx] = hr; d_wr[idx] = wr; d_act[idx] = act;
}

// =====================================================================
// Kernel 2: streaming focal base term over the whole hm tensor.
// grid = 2560 blocks x 256 threads x 8 float4 per thread (exact cover).
// =====================================================================
__global__ void __launch_bounds__(256) base_kernel(const float4* __restrict__ hm4) {
    int idx = blockIdx.x * (256*8) + threadIdx.x;
    float4 v[8];
#pragma unroll
    for (int u = 0; u < 8; u++) v[u] = __ldg(&hm4[idx + u*256]);
    float lsum = 0.0f;
#pragma unroll
    for (int u = 0; u < 8; u++) {
        float p;
        lsum += focal_neg_base(v[u].x, p);
        lsum += focal_neg_base(v[u].y, p);
        lsum += focal_neg_base(v[u].z, p);
        lsum += focal_neg_base(v[u].w, p);
    }
    for (int off = 16; off; off >>= 1)
        lsum += __shfl_down_sync(0xffffffffu, lsum, off);
    __shared__ float r[8];
    int w = threadIdx.x >> 5;
    if ((threadIdx.x & 31) == 0) r[w] = lsum;
    __syncthreads();
    if (threadIdx.x == 0) {
        float a = 0.0f;
#pragma unroll
        for (int i = 0; i < 8; i++) a += r[i];
        atomicAdd(&d_acc_hm, (double)a);
    }
}

// =====================================================================
// Kernel 3: sparse corrections + wh/IoU.  grid=(OH, BATCH), 128 threads.
// One pixel per thread (R2-proven shape); no dense class loop.
// =====================================================================
__global__ void __launch_bounds__(128) sparse_kernel(const float* __restrict__ hm,
                                                     const float* __restrict__ wh) {
    int y = blockIdx.x, b = blockIdx.y, x = threadIdx.x;
    int m = threadIdx.x;
    int lane = m & 31;

    __shared__ float sgy[KBOX];
    __shared__ float sx1[KBOX], sy1s[KBOX], sx2[KBOX], sy2s[KBOX];
    __shared__ float scoef[KBOX], si2sx[KBOX];
    __shared__ int   scx[KBOX], swr[KBOX], scls[KBOX];
    __shared__ short slist[KBOX];
    __shared__ int   s_n;

    int base = b*KBOX + m;
    {
        float i2sy = d_i2sy[base];
        int cy = d_cy[base], hr = d_hr[base], act = d_act[base];
        int dy = y - cy;
        int rowcov = act && (abs(dy) <= hr);
        sgy[m] = rowcov ? __expf(-(float)(dy*dy) * i2sy) : 0.0f;
        sx1[m] = d_bx1[base]; sy1s[m] = d_by1[base];
        sx2[m] = d_bx2[base]; sy2s[m] = d_by2[base];
        scoef[m] = d_coef[base]; si2sx[m] = d_i2sx[base];
        scx[m] = d_cx[base]; swr[m] = d_wr[base]; scls[m] = d_cls[base];
    }
    __syncthreads();
    // warp 0 builds row list by ballot compaction
    if (m < 32) {
        int nn = 0;
#pragma unroll
        for (int chunk = 0; chunk < 4; chunk++) {
            int j = chunk*32 + lane;
            bool p = sgy[j] > 0.0f;
            unsigned mb = __ballot_sync(0xffffffffu, p);
            int pos = nn + __popc(mb & ((1u << lane) - 1u));
            if (p) slist[pos] = (short)j;
            nn += __popc(mb);
        }
        if (lane == 0) s_n = nn;
    }
    __syncthreads();
    int n = s_n;

    // ---- coverage mask + winner ----
    unsigned covm[4] = {0u,0u,0u,0u};
    int e_w = -1;
    for (int e = 0; e < n; e++) {
        int j = slist[e];
        int dx = x - scx[j];
        if (abs(dx) <= swr[j]) {
            covm[e >> 5] |= 1u << (e & 31);
            e_w = e;
        }
    }

    float lsum = 0.0f;
    int   lnp  = 0;
    const float* hmr = hm + (((size_t)b*NUMC)*OH + y)*OW + x;

    // ---- footprint corrections ----
    for (int e = 0; e < n; e++) {
        if (!((covm[e >> 5] >> (e & 31)) & 1u)) continue;
        int j = slist[e];
        int c = scls[j];
        float dxf = (float)(x - scx[j]);
        float g = sgy[j] * __expf(-dxf*dxf * si2sx[j]);
        bool rep = true;
        for (int e2 = 0; e2 < n; e2++) {
            if (e2 == e) continue;
            if (!((covm[e2 >> 5] >> (e2 & 31)) & 1u)) continue;
            int j2 = slist[e2];
            if (scls[j2] != c) continue;
            float dx2 = (float)(x - scx[j2]);
            float g2 = sgy[j2] * __expf(-dx2*dx2 * si2sx[j2]);
            if (g2 > g || (g2 == g && e2 < e)) { rep = false; break; }
        }
        if (!rep) continue;
        float xv = hmr[(size_t)c * PLANE];
        float p;
        float u = focal_neg_base(xv, p);
        if (g == 1.0f) {
            float omp = 1.0f - p;
            float vv = __logf(p) * omp * omp;
            lsum += vv - u;
            lnp++;
        } else {
            float omh = 1.0f - g;
            float w4 = omh * omh; w4 *= w4;
            lsum += u * (w4 - 1.0f);
        }
    }

    // ---- wh / IoU at winner pixels ----
    float lwhn = 0.0f, lrw = 0.0f;
    if (e_w >= 0) {
        int j = slist[e_w];
        float dxf = (float)(x - scx[j]);
        float g = sgy[j] * __expf(-dxf*dxf * si2sx[j]);
        float rw = g * scoef[j];
        size_t pbase = (((size_t)b*4)*OH + y)*OW + x;
        float pl = wh[pbase            ] * 16.0f;
        float pt = wh[pbase +   PLANE  ] * 16.0f;
        float pr = wh[pbase + 2*PLANE  ] * 16.0f;
        float pb = wh[pbase + 3*PLANE  ] * 16.0f;
        float xs = (float)x * 4.0f, ys = (float)y * 4.0f;
        float tl = xs - sx1[j];
        float tt = ys - sy1s[j];
        float tr = sx2[j] - xs;
        float tb = sy2s[j] - ys;
        float ta = (tl + tr) * (tt + tb);
        float pa = (pl + pr) * (pt + pb);
        float wi = fminf(pl, tl) + fminf(pr, tr);
        float hi = fminf(pt, tt) + fminf(pb, tb);
        float ai = wi * hi;
        float au = ta + pa - ai;
        float iou = (ai + 1.0f) / (au + 1.0f);
        lwhn = (rw > 0.0f) ? (1.0f - iou) * rw : 0.0f;
        lrw = rw;
    }

    // ---- block reduce -> double atomics ----
    for (int off = 16; off; off >>= 1) {
        lsum += __shfl_down_sync(0xffffffffu, lsum, off);
        lwhn += __shfl_down_sync(0xffffffffu, lwhn, off);
        lrw  += __shfl_down_sync(0xffffffffu, lrw,  off);
        lnp  += __shfl_down_sync(0xffffffffu, lnp,  off);
    }
    __shared__ float r0[4], r1[4], r2[4];
    __shared__ int   r3[4];
    int wid = m >> 5;
    if (lane == 0) { r0[wid]=lsum; r1[wid]=lwhn; r2[wid]=lrw; r3[wid]=lnp; }
    __syncthreads();
    if (m == 0) {
        float a=0.f, c1=0.f, c2=0.f; int np=0;
        for (int i = 0; i < 4; i++) { a+=r0[i]; c1+=r1[i]; c2+=r2[i]; np+=r3[i]; }
        atomicAdd(&d_acc_hm,  (double)a);
        atomicAdd(&d_acc_whn, (double)c1);
        atomicAdd(&d_acc_rw,  (double)c2);
        atomicAdd(&d_acc_np,  np);
    }
}

__global__ void final_kernel(float* out) {
    double hm_sum = d_acc_hm;
    int np = d_acc_np;
    double hml;
    if (np > 0) hml = -hm_sum / (double)(np < 1 ? 1 : np);
    else        hml = -hm_sum;
    double whl = d_acc_whn / fmax(d_acc_rw, 1.0);
    out[0] = (float)(hml + whl);
}

extern "C" void kernel_launch(void* const* d_in, const int* in_sizes, int n_in,
                              void* d_out, int out_size) {
    const float* hm   = (const float*)d_in[0];
    const float* wh   = (const float*)d_in[1];
    const float* tgt  = (const float*)d_in[2];
    const void*  mask = (const void*)d_in[3];
    float* out = (float*)d_out;
    (void)in_sizes; (void)n_in; (void)out_size;

    prep_kernel<<<BATCH, KBOX>>>(tgt, mask);
    base_kernel<<<BASE_BLK, 256>>>((const float4*)hm);
    sparse_kernel<<<dim3(OH, BATCH), 128>>>(hm, wh);
    final_kernel<<<1, 1>>>(out);
}